// round 1
// baseline (speedup 1.0000x reference)
#include <cuda_runtime.h>
#include <cuda_bf16.h>
#include <cstdint>

// Problem constants
#define B_SZ   16
#define CIN    512
#define L_IN   4000
#define KW     16
#define STRIDE 8
#define L_OUT  31992            // (4000-1)*8 - 16 + 16

// Intermediate z[b][m][k] = sum_cin x[b,cin,m] * W_b[cin,k]
__device__ float g_zbuf[B_SZ * L_IN * KW];   // 4.1 MB scratch (static, allowed)

// ---------------------------------------------------------------------------
// Kernel 1: per-sample skinny GEMM  z = x^T @ W_b  using packed f32x2 FFMA.
// Grid: (8 m-tiles, 16 batch), 256 threads. Each thread owns a consecutive
// m-pair (one LDG.64 per cin), 16 packed accumulators.
// ---------------------------------------------------------------------------
extern "C" __global__ void __launch_bounds__(256, 1)
zgemm_kernel(const float* __restrict__ x,
             const float* __restrict__ t60s,
             const float* __restrict__ kw)
{
    extern __shared__ unsigned long long Wd[];   // [CIN*KW] duplicated {w,w}, 64 KB

    const int b = blockIdx.y;
    // idx = round(t60*100) - 10, tiled so b>=8 reuses t60s[b-8]
    const int idxb = (int)rintf(t60s[b & 7] * 100.0f) - 10;
    const float* wsrc = kw + (size_t)idxb * (CIN * KW);

    // Fill smem with duplicated weights: Wd[i] = {w, w}
    for (int i = threadIdx.x; i < CIN * KW; i += 256) {
        float w = wsrc[i];
        unsigned long long d;
        asm("mov.b64 %0, {%1, %2};" : "=l"(d) : "f"(w), "f"(w));
        Wd[i] = d;
    }
    __syncthreads();

    const int m = blockIdx.x * 512 + threadIdx.x * 2;   // consecutive m-pair
    if (m >= L_IN) return;                              // last tile guard (pairs stay aligned)

    const float* xp = x + (size_t)b * CIN * L_IN + m;

    unsigned long long acc[KW];
#pragma unroll
    for (int k = 0; k < KW; ++k) acc[k] = 0ULL;         // {0.f, 0.f}

#pragma unroll 4
    for (int cin = 0; cin < CIN; ++cin) {
        float2 xf = *(const float2*)(xp + (size_t)cin * L_IN);
        unsigned long long xv;
        asm("mov.b64 %0, {%1, %2};" : "=l"(xv) : "f"(xf.x), "f"(xf.y));

        const ulonglong2* wrow = (const ulonglong2*)(Wd + cin * KW);
#pragma unroll
        for (int j = 0; j < 8; ++j) {                   // 8 x LDS.128 -> 16 FFMA2
            ulonglong2 wv = wrow[j];
            asm("fma.rn.f32x2 %0, %1, %2, %0;" : "+l"(acc[2*j  ]) : "l"(xv), "l"(wv.x));
            asm("fma.rn.f32x2 %0, %1, %2, %0;" : "+l"(acc[2*j+1]) : "l"(xv), "l"(wv.y));
        }
    }

    // Unpack and store: 16 consecutive floats per m-column -> float4 stores
    float lo[KW], hi[KW];
#pragma unroll
    for (int k = 0; k < KW; ++k)
        asm("mov.b64 {%0, %1}, %2;" : "=f"(lo[k]), "=f"(hi[k]) : "l"(acc[k]));

    float* za = g_zbuf + ((size_t)b * L_IN + m) * KW;   // column m
    float* zb = za + KW;                                // column m+1
#pragma unroll
    for (int j = 0; j < 4; ++j) {
        ((float4*)za)[j] = make_float4(lo[4*j], lo[4*j+1], lo[4*j+2], lo[4*j+3]);
        ((float4*)zb)[j] = make_float4(hi[4*j], hi[4*j+1], hi[4*j+2], hi[4*j+3]);
    }
}

// ---------------------------------------------------------------------------
// Kernel 2: y[b, 8m+p] = z[b, m+1, p] + z[b, m, p+8]   (no boundary cases)
// ---------------------------------------------------------------------------
extern "C" __global__ void __launch_bounds__(256)
combine_kernel(float* __restrict__ out)
{
    const int r = blockIdx.x * 256 + threadIdx.x;
    const int b = blockIdx.y;
    if (r >= L_OUT) return;
    const int m = r >> 3;
    const int p = r & 7;
    const float* zb = g_zbuf + (size_t)b * L_IN * KW;
    out[(size_t)b * L_OUT + r] = zb[(m + 1) * KW + p] + zb[m * KW + p + 8];
}

// ---------------------------------------------------------------------------
extern "C" void kernel_launch(void* const* d_in, const int* in_sizes, int n_in,
                              void* d_out, int out_size)
{
    const float* x    = (const float*)d_in[0];   // (16, 512, 4000) f32
    const float* t60s = (const float*)d_in[1];   // (8,)            f32
    const float* kw   = (const float*)d_in[2];   // (41, 512, 1, 16) f32
    float*       out  = (float*)d_out;           // (16, 1, 31992)  f32

    static bool attr_set = false;
    if (!attr_set) {
        cudaFuncSetAttribute(zgemm_kernel,
                             cudaFuncAttributeMaxDynamicSharedMemorySize,
                             CIN * KW * sizeof(unsigned long long));
        attr_set = true;
    }

    dim3 g1(8, B_SZ);            // 8 m-tiles of 512 columns, 16 samples
    zgemm_kernel<<<g1, 256, CIN * KW * sizeof(unsigned long long)>>>(x, t60s, kw);

    dim3 g2((L_OUT + 255) / 256, B_SZ);
    combine_kernel<<<g2, 256>>>(out);
}

// round 3
// speedup vs baseline: 1.3519x; 1.3519x over previous
#include <cuda_runtime.h>
#include <cuda_bf16.h>
#include <cstdint>

// Problem constants
#define B_SZ   16
#define CIN    512
#define L_IN   4000
#define KW     16
#define STRIDE 8
#define L_OUT  31992            // (4000-1)*8 - 16 + 16
#define CSPLIT 2
#define CHALF  (CIN / CSPLIT)   // 256

// Intermediate z[half][b][m][k] = sum_{cin in half} x[b,cin,m] * W_b[cin,k]
__device__ float g_zbuf[CSPLIT * B_SZ * L_IN * KW];   // 8.2 MB scratch

// ---------------------------------------------------------------------------
// Kernel 1: per-sample skinny GEMM  z = x^T @ W_b  using packed f32x2 FFMA.
// Grid: (8 m-tiles, 16 batch, 2 cin-halves), 256 threads. Each thread owns a
// consecutive m-pair (LDG.64 per cin), 16 packed accumulators. 32 KB smem of
// duplicated {w,w} weights -> 2 blocks/SM resident, unroll 8 for MLP.
// ---------------------------------------------------------------------------
extern "C" __global__ void __launch_bounds__(256)
zgemm_kernel(const float* __restrict__ x,
             const float* __restrict__ t60s,
             const float* __restrict__ kw)
{
    __shared__ unsigned long long Wd[CHALF * KW];     // duplicated {w,w}, 32 KB

    const int b    = blockIdx.y;
    const int half = blockIdx.z;
    // idx = round(t60*100) - 10, tiled so b>=8 reuses t60s[b-8]
    const int idxb = (int)rintf(t60s[b & 7] * 100.0f) - 10;
    const float* wsrc = kw + (size_t)idxb * (CIN * KW) + half * (CHALF * KW);

    for (int i = threadIdx.x; i < CHALF * KW; i += 256) {
        float w = wsrc[i];
        unsigned long long d;
        asm("mov.b64 %0, {%1, %2};" : "=l"(d) : "f"(w), "f"(w));
        Wd[i] = d;
    }
    __syncthreads();

    const int m = blockIdx.x * 512 + threadIdx.x * 2;   // consecutive m-pair
    if (m >= L_IN) return;   // last-tile guard (after the only __syncthreads)

    const float* xp = x + (size_t)b * CIN * L_IN + (size_t)half * CHALF * L_IN + m;

    unsigned long long acc[KW];
#pragma unroll
    for (int k = 0; k < KW; ++k) acc[k] = 0ULL;         // {0.f, 0.f}

#pragma unroll 8
    for (int cin = 0; cin < CHALF; ++cin) {
        float2 xf = *(const float2*)(xp + (size_t)cin * L_IN);
        unsigned long long xv;
        asm("mov.b64 %0, {%1, %2};" : "=l"(xv) : "f"(xf.x), "f"(xf.y));

        const ulonglong2* wrow = (const ulonglong2*)(Wd + cin * KW);
#pragma unroll
        for (int j = 0; j < 8; ++j) {                   // 8 x LDS.128 -> 16 FFMA2
            ulonglong2 wv = wrow[j];
            asm("fma.rn.f32x2 %0, %1, %2, %0;" : "+l"(acc[2*j  ]) : "l"(xv), "l"(wv.x));
            asm("fma.rn.f32x2 %0, %1, %2, %0;" : "+l"(acc[2*j+1]) : "l"(xv), "l"(wv.y));
        }
    }

    // Unpack and store: 16 consecutive floats per m-column -> float4 stores
    float lo[KW], hi[KW];
#pragma unroll
    for (int k = 0; k < KW; ++k)
        asm("mov.b64 {%0, %1}, %2;" : "=f"(lo[k]), "=f"(hi[k]) : "l"(acc[k]));

    float* za = g_zbuf + (((size_t)half * B_SZ + b) * L_IN + m) * KW;   // column m
    float* zb = za + KW;                                                // column m+1
#pragma unroll
    for (int j = 0; j < 4; ++j) {
        ((float4*)za)[j] = make_float4(lo[4*j], lo[4*j+1], lo[4*j+2], lo[4*j+3]);
        ((float4*)zb)[j] = make_float4(hi[4*j], hi[4*j+1], hi[4*j+2], hi[4*j+3]);
    }
}

// ---------------------------------------------------------------------------
// Kernel 2: y[b, 8m+p] = sum_halves ( z[m+1, p] + z[m, p+8] )
// ---------------------------------------------------------------------------
extern "C" __global__ void __launch_bounds__(256)
combine_kernel(float* __restrict__ out)
{
    const int r = blockIdx.x * 256 + threadIdx.x;
    const int b = blockIdx.y;
    if (r >= L_OUT) return;
    const int m = r >> 3;
    const int p = r & 7;
    const float* z0 = g_zbuf + (size_t)b * L_IN * KW;
    const float* z1 = g_zbuf + ((size_t)B_SZ + b) * L_IN * KW;
    out[(size_t)b * L_OUT + r] =
        (z0[(m + 1) * KW + p] + z0[m * KW + p + 8]) +
        (z1[(m + 1) * KW + p] + z1[m * KW + p + 8]);
}

// ---------------------------------------------------------------------------
extern "C" void kernel_launch(void* const* d_in, const int* in_sizes, int n_in,
                              void* d_out, int out_size)
{
    const float* x    = (const float*)d_in[0];   // (16, 512, 4000) f32
    const float* t60s = (const float*)d_in[1];   // (8,)            f32
    const float* kw   = (const float*)d_in[2];   // (41, 512, 1, 16) f32
    float*       out  = (float*)d_out;           // (16, 1, 31992)  f32

    dim3 g1(8, B_SZ, CSPLIT);    // 8 m-tiles of 512 columns, 16 samples, 2 halves
    zgemm_kernel<<<g1, 256>>>(x, t60s, kw);

    dim3 g2((L_OUT + 255) / 256, B_SZ);
    combine_kernel<<<g2, 256>>>(out);
}

// round 4
// speedup vs baseline: 1.6691x; 1.2346x over previous
#include <cuda_runtime.h>
#include <cuda_bf16.h>
#include <cstdint>

// Problem constants
#define B_SZ   16
#define CIN    512
#define L_IN   4000
#define KW     16
#define STRIDE 8
#define L_OUT  31992            // (4000-1)*8 - 16 + 16
#define CSPLIT 2
#define CHALF  (CIN / CSPLIT)   // 256

// Intermediate z[half][b][m][k] = sum_{cin in half} x[b,cin,m] * W_b[cin,k]
__device__ float g_zbuf[CSPLIT * B_SZ * L_IN * KW];   // 8.2 MB scratch

// ---------------------------------------------------------------------------
// Kernel 1: per-sample skinny GEMM  z = x^T @ W_b  using packed f32x2 FFMA.
// Grid: (8 m-tiles, 16 batch, 2 cin-halves), 256 threads. Each thread owns a
// consecutive m-pair (LDG.64 per cin), 16 packed accumulators. 32 KB smem,
// __launch_bounds__(256,2) forces regs<=128 -> 2 blocks/SM -> 4 warps/SMSP,
// unroll 8 for MLP -> ~4.7 MB in flight chip-wide (HBM-saturating).
// ---------------------------------------------------------------------------
extern "C" __global__ void __launch_bounds__(256, 2)
zgemm_kernel(const float* __restrict__ x,
             const float* __restrict__ t60s,
             const float* __restrict__ kw)
{
    __shared__ unsigned long long Wd[CHALF * KW];     // duplicated {w,w}, 32 KB

    const int b    = blockIdx.y;
    const int half = blockIdx.z;
    // idx = round(t60*100) - 10, tiled so b>=8 reuses t60s[b-8]
    const int idxb = (int)rintf(t60s[b & 7] * 100.0f) - 10;
    const float* wsrc = kw + (size_t)idxb * (CIN * KW) + half * (CHALF * KW);

    for (int i = threadIdx.x; i < CHALF * KW; i += 256) {
        float w = wsrc[i];
        unsigned long long d;
        asm("mov.b64 %0, {%1, %2};" : "=l"(d) : "f"(w), "f"(w));
        Wd[i] = d;
    }
    __syncthreads();

    const int m = blockIdx.x * 512 + threadIdx.x * 2;   // consecutive m-pair
    if (m >= L_IN) return;   // last-tile guard (after the only __syncthreads)

    const float* xp = x + (size_t)b * CIN * L_IN + (size_t)half * CHALF * L_IN + m;

    unsigned long long acc[KW];
#pragma unroll
    for (int k = 0; k < KW; ++k) acc[k] = 0ULL;         // {0.f, 0.f}

#pragma unroll 8
    for (int cin = 0; cin < CHALF; ++cin) {
        float2 xf = *(const float2*)(xp + (size_t)cin * L_IN);
        unsigned long long xv;
        asm("mov.b64 %0, {%1, %2};" : "=l"(xv) : "f"(xf.x), "f"(xf.y));

        const ulonglong2* wrow = (const ulonglong2*)(Wd + cin * KW);
#pragma unroll
        for (int j = 0; j < 8; ++j) {                   // 8 x LDS.128 -> 16 FFMA2
            ulonglong2 wv = wrow[j];
            asm("fma.rn.f32x2 %0, %1, %2, %0;" : "+l"(acc[2*j  ]) : "l"(xv), "l"(wv.x));
            asm("fma.rn.f32x2 %0, %1, %2, %0;" : "+l"(acc[2*j+1]) : "l"(xv), "l"(wv.y));
        }
    }

    // Unpack and store: 16 consecutive floats per m-column -> float4 stores
    float lo[KW], hi[KW];
#pragma unroll
    for (int k = 0; k < KW; ++k)
        asm("mov.b64 {%0, %1}, %2;" : "=f"(lo[k]), "=f"(hi[k]) : "l"(acc[k]));

    float* za = g_zbuf + (((size_t)half * B_SZ + b) * L_IN + m) * KW;   // column m
    float* zb = za + KW;                                                // column m+1
#pragma unroll
    for (int j = 0; j < 4; ++j) {
        ((float4*)za)[j] = make_float4(lo[4*j], lo[4*j+1], lo[4*j+2], lo[4*j+3]);
        ((float4*)zb)[j] = make_float4(hi[4*j], hi[4*j+1], hi[4*j+2], hi[4*j+3]);
    }
}

// ---------------------------------------------------------------------------
// Kernel 2: one thread per m-column (m in [0, 3998]) produces 8 outputs:
//   y[b, 8m+p] = sum_halves ( z[m+1, p] + z[m, p+8] ),  p = 0..7
// Reads only the needed half-columns (front half of col m+1, back half of
// col m) -> every z byte read exactly once, fully coalesced LDG/STG.128.
// ---------------------------------------------------------------------------
extern "C" __global__ void __launch_bounds__(256)
combine_kernel(float* __restrict__ out)
{
    const int mcol = blockIdx.x * 256 + threadIdx.x;
    const int b    = blockIdx.y;
    if (mcol > L_IN - 2) return;                       // m <= 3998

    const float4* z0 = (const float4*)(g_zbuf + ((size_t)b * L_IN) * KW);
    const float4* z1 = (const float4*)(g_zbuf + (((size_t)B_SZ + b) * L_IN) * KW);

    // column m: 4 float4 -> need elements [8..15] = float4 idx 2,3
    // column m+1: need elements [0..7]           = float4 idx 0,1
    float4 a0 = z0[(mcol + 1) * 4 + 0];
    float4 a1 = z0[(mcol + 1) * 4 + 1];
    float4 b0 = z0[mcol * 4 + 2];
    float4 b1 = z0[mcol * 4 + 3];
    float4 c0 = z1[(mcol + 1) * 4 + 0];
    float4 c1 = z1[(mcol + 1) * 4 + 1];
    float4 d0 = z1[mcol * 4 + 2];
    float4 d1 = z1[mcol * 4 + 3];

    float4 o0 = make_float4((a0.x + b0.x) + (c0.x + d0.x),
                            (a0.y + b0.y) + (c0.y + d0.y),
                            (a0.z + b0.z) + (c0.z + d0.z),
                            (a0.w + b0.w) + (c0.w + d0.w));
    float4 o1 = make_float4((a1.x + b1.x) + (c1.x + d1.x),
                            (a1.y + b1.y) + (c1.y + d1.y),
                            (a1.z + b1.z) + (c1.z + d1.z),
                            (a1.w + b1.w) + (c1.w + d1.w));

    float4* op = (float4*)(out + (size_t)b * L_OUT + mcol * 8);
    op[0] = o0;
    op[1] = o1;
}

// ---------------------------------------------------------------------------
extern "C" void kernel_launch(void* const* d_in, const int* in_sizes, int n_in,
                              void* d_out, int out_size)
{
    const float* x    = (const float*)d_in[0];   // (16, 512, 4000) f32
    const float* t60s = (const float*)d_in[1];   // (8,)            f32
    const float* kw   = (const float*)d_in[2];   // (41, 512, 1, 16) f32
    float*       out  = (float*)d_out;           // (16, 1, 31992)  f32

    dim3 g1(8, B_SZ, CSPLIT);    // 8 m-tiles of 512 columns, 16 samples, 2 halves
    zgemm_kernel<<<g1, 256>>>(x, t60s, kw);

    dim3 g2((L_IN - 1 + 255) / 256, B_SZ);       // 3999 m-columns per sample
    combine_kernel<<<g2, 256>>>(out);
}